// round 11
// baseline (speedup 1.0000x reference)
#include <cuda_runtime.h>
#include <cuda_fp16.h>
#include <cstdint>

#define NUM_NEURONS 8192
#define INPUT_SIZE  8192
#define BATCH       2048

#define THREADS 1024
#define NPT     8                  // neurons per thread (2 groups of 4)
#define NGROUP  (NPT / 4)          // 2
#define GRID    148                // persistent: 1 block per SM
#define PAIRS   (BATCH / 2)        // 1024 row-pairs
#define PAIR_BYTES (2 * INPUT_SIZE * 4)   // 64 KB fp32 pair
#define NBUF    2

// Per-neuron collapsed coefficients: out = A + B*a1 + C*a2 + D*a1*a2
__device__ float4 g_coeff[NUM_NEURONS];

// Per-op affine coefficients (const, a1, a2, a1*a2) for the 16 logic ops.
__constant__ float4 c_op[16] = {
    {0.f,  0.f,  0.f,  0.f},   //  0: 0
    {0.f,  0.f,  0.f,  1.f},   //  1: p
    {0.f,  1.f,  0.f, -1.f},   //  2: a1 - p
    {0.f,  1.f,  0.f,  0.f},   //  3: a1
    {0.f,  0.f,  1.f, -1.f},   //  4: a2 - p
    {0.f,  0.f,  1.f,  0.f},   //  5: a2
    {0.f,  1.f,  1.f, -2.f},   //  6: a1 + a2 - 2p
    {0.f,  1.f,  1.f, -1.f},   //  7: a1 + a2 - p
    {1.f, -1.f, -1.f,  1.f},   //  8: 1 - (a1 + a2 - p)
    {1.f, -1.f, -1.f,  2.f},   //  9: 1 - (a1 + a2 - 2p)
    {1.f,  0.f, -1.f,  0.f},   // 10: 1 - a2
    {1.f,  0.f, -1.f,  1.f},   // 11: 1 - a2 + p
    {1.f, -1.f,  0.f,  0.f},   // 12: 1 - a1
    {1.f, -1.f,  0.f,  1.f},   // 13: 1 - a1 + p
    {1.f,  0.f,  0.f, -1.f},   // 14: 1 - p
    {1.f,  0.f,  0.f,  0.f},   // 15: 1
};

// ---------------------------------------------------------------------------
// Warp-parallel coefficient precompute: 16 lanes per neuron (one per op).
// One coalesced load + one exp per lane; softmax and the coefficient dot
// products are width-16 shuffle reductions. 131072 threads -> full chip.
// ---------------------------------------------------------------------------
__global__ void coeff_kernel(const float* __restrict__ w) {
    const int gt = blockIdx.x * blockDim.x + threadIdx.x;
    const int n = gt >> 4;
    const int j = gt & 15;
    if (n >= NUM_NEURONS) return;

    const float wv = __ldg(&w[(n << 4) + j]);

    float m = wv;
#pragma unroll
    for (int o = 8; o; o >>= 1) m = fmaxf(m, __shfl_xor_sync(0xFFFFFFFFu, m, o, 16));
    const float e = __expf(wv - m);
    float s = e;
#pragma unroll
    for (int o = 8; o; o >>= 1) s += __shfl_xor_sync(0xFFFFFFFFu, s, o, 16);
    const float p = e / s;

    const float4 c = c_op[j];
    float A = p * c.x, B = p * c.y, C = p * c.z, D = p * c.w;
#pragma unroll
    for (int o = 8; o; o >>= 1) {
        A += __shfl_xor_sync(0xFFFFFFFFu, A, o, 16);
        B += __shfl_xor_sync(0xFFFFFFFFu, B, o, 16);
        C += __shfl_xor_sync(0xFFFFFFFFu, C, o, 16);
        D += __shfl_xor_sync(0xFFFFFFFFu, D, o, 16);
    }
    if (j == 0) g_coeff[n] = make_float4(A, B, C, D);
}

// ---------------------------------------------------------------------------
// PTX helpers (mbarrier + 1D TMA bulk copy)
// ---------------------------------------------------------------------------
__device__ __forceinline__ uint32_t smem_u32(const void* p) {
    uint32_t a;
    asm("{ .reg .u64 t; cvta.to.shared.u64 t, %1; cvt.u32.u64 %0, t; }"
        : "=r"(a) : "l"(p));
    return a;
}
__device__ __forceinline__ void mbar_init(uint32_t m, uint32_t cnt) {
    asm volatile("mbarrier.init.shared.b64 [%0], %1;" :: "r"(m), "r"(cnt) : "memory");
}
__device__ __forceinline__ void mbar_expect_tx(uint32_t m, uint32_t bytes) {
    asm volatile("mbarrier.arrive.expect_tx.shared.b64 _, [%0], %1;"
                 :: "r"(m), "r"(bytes) : "memory");
}
__device__ __forceinline__ void mbar_wait(uint32_t m, uint32_t phase) {
    asm volatile(
        "{\n\t.reg .pred P;\n\t"
        "WL_%=:\n\t"
        "mbarrier.try_wait.parity.acquire.cta.shared::cta.b64 P, [%0], %1, 0x989680;\n\t"
        "@P bra WD_%=;\n\t"
        "bra WL_%=;\n\t"
        "WD_%=:\n\t}"
        :: "r"(m), "r"(phase) : "memory");
}
__device__ __forceinline__ void tma_bulk_g2s(uint32_t dst_smem, const void* src,
                                             uint32_t bytes, uint32_t mbar) {
    asm volatile(
        "cp.async.bulk.shared::cluster.global.mbarrier::complete_tx::bytes "
        "[%0], [%1], %2, [%3];"
        :: "r"(dst_smem), "l"(src), "r"(bytes), "r"(mbar) : "memory");
}

// ---------------------------------------------------------------------------
// Persistent main kernel (R9 structure — best measured dur_us).
// grid=148, 1 block/SM, 1024 threads. Per pair: TMA brings the fp32 row pair
// (64KB); a conflict-free convert pass packs it into half2 {row0[i], row1[i]}
// (32KB). Gathers fetch BOTH rows with a single LDS.32. Math stays fp32.
// The fp32 buffer is free after the convert barrier, so the TMA for pair k+2
// is issued there and overlaps the gather/compute of pair k.
// ---------------------------------------------------------------------------
__global__ __launch_bounds__(THREADS, 1) void logic_kernel(
    const float* __restrict__ x,
    const int*   __restrict__ idx,
    float* __restrict__ out)
{
    extern __shared__ __align__(128) char smem[];
    float*   buf0 = reinterpret_cast<float*>(smem);                  // 64 KB fp32
    float*   buf1 = reinterpret_cast<float*>(smem + PAIR_BYTES);     // 64 KB fp32
    __half2* xh   = reinterpret_cast<__half2*>(smem + 2 * PAIR_BYTES); // 32 KB
    const uint32_t mbar0 = smem_u32(smem + 2 * PAIR_BYTES + INPUT_SIZE * 4);
    const uint32_t mbar1 = mbar0 + 8;

    const int tid = threadIdx.x;
    const int bid = blockIdx.x;

    // --- Preload idx (packed u16 pairs) + coefficients into registers ---
    uint32_t pidx[NPT];
    float4   cf[NPT];
    const int4* idx4 = reinterpret_cast<const int4*>(idx);  // 2 neurons per int4
#pragma unroll
    for (int g = 0; g < NGROUP; g++) {
        int nbase = g * (4 * THREADS) + tid * 4;   // 4 consecutive neurons
        int4 ia = __ldg(&idx4[nbase / 2]);         // neurons nbase, nbase+1
        int4 ib = __ldg(&idx4[nbase / 2 + 1]);     // neurons nbase+2, nbase+3
        pidx[g * 4 + 0] = (uint32_t)ia.x | ((uint32_t)ia.y << 16);
        pidx[g * 4 + 1] = (uint32_t)ia.z | ((uint32_t)ia.w << 16);
        pidx[g * 4 + 2] = (uint32_t)ib.x | ((uint32_t)ib.y << 16);
        pidx[g * 4 + 3] = (uint32_t)ib.z | ((uint32_t)ib.w << 16);
#pragma unroll
        for (int u = 0; u < 4; u++) cf[g * 4 + u] = g_coeff[nbase + u];
    }

    if (tid == 0) { mbar_init(mbar0, 1); mbar_init(mbar1, 1); }
    __syncthreads();

    const int npairs = (PAIRS - bid + GRID - 1) / GRID;   // 6 or 7

    // --- Prologue: issue first two TMA loads ---
    if (tid == 0) {
        if (npairs > 0) {
            mbar_expect_tx(mbar0, PAIR_BYTES);
            tma_bulk_g2s(smem_u32(buf0), x + (size_t)bid * 2 * INPUT_SIZE,
                         PAIR_BYTES, mbar0);
        }
        if (npairs > 1) {
            mbar_expect_tx(mbar1, PAIR_BYTES);
            tma_bulk_g2s(smem_u32(buf1), x + (size_t)(bid + GRID) * 2 * INPUT_SIZE,
                         PAIR_BYTES, mbar1);
        }
    }

    uint32_t phases = 0;   // bit b = current wait parity of buffer b

    for (int k = 0; k < npairs; k++) {
        const int b = k & 1;
        const float* bf = b ? buf1 : buf0;
        const uint32_t mb = b ? mbar1 : mbar0;

        mbar_wait(mb, (phases >> b) & 1u);
        phases ^= (1u << b);

        // --- Convert pass: pack {row0[c], row1[c]} -> half2. Conflict-free. ---
#pragma unroll
        for (int c = tid; c < INPUT_SIZE; c += THREADS)
            xh[c] = __floats2half2_rn(bf[c], bf[c + INPUT_SIZE]);
        __syncthreads();   // xh ready; fp32 buffer b is now dead

        // fp32 buffer b free -> prefetch pair k+2 immediately (overlaps gather)
        if (tid == 0 && k + 2 < npairs) {
            mbar_expect_tx(mb, PAIR_BYTES);
            tma_bulk_g2s(smem_u32(b ? buf1 : buf0),
                         x + (size_t)(bid + (k + 2) * GRID) * 2 * INPUT_SIZE,
                         PAIR_BYTES, mb);
        }

        const int p = bid + k * GRID;
        float4* o0 = reinterpret_cast<float4*>(out + (size_t)(2 * p)     * NUM_NEURONS);
        float4* o1 = reinterpret_cast<float4*>(out + (size_t)(2 * p + 1) * NUM_NEURONS);

#pragma unroll
        for (int g = 0; g < NGROUP; g++) {
            float4 r0, r1;
            float* q0 = reinterpret_cast<float*>(&r0);
            float* q1 = reinterpret_cast<float*>(&r1);
#pragma unroll
            for (int u = 0; u < 4; u++) {
                const uint32_t pk = pidx[g * 4 + u];
                const int i1 = pk & 0xFFFFu;
                const int i2 = pk >> 16;
                const float2 a = __half22float2(xh[i1]);   // {row0, row1} @ i1
                const float2 c2 = __half22float2(xh[i2]);  // {row0, row1} @ i2
                const float4 c = cf[g * 4 + u];
                q0[u] = fmaf(a.x, fmaf(c2.x, c.w, c.y), fmaf(c2.x, c.z, c.x));
                q1[u] = fmaf(a.y, fmaf(c2.y, c.w, c.y), fmaf(c2.y, c.z, c.x));
            }
            const int o = g * THREADS + tid;   // coalesced float4 stores
            o0[o] = r0;
            o1[o] = r1;
        }

        __syncthreads();   // all reads of xh done before next pair's convert
    }
}

extern "C" void kernel_launch(void* const* d_in, const int* in_sizes, int n_in,
                              void* d_out, int out_size) {
    const float* x    = (const float*)d_in[0];   // [2048, 8192] f32
    const float* w    = (const float*)d_in[1];   // [8192, 16]   f32
    const int*   conn = (const int*)d_in[2];     // [8192, 2]    i32
    float* out = (float*)d_out;                  // [2048, 8192] f32

    const int smem = NBUF * PAIR_BYTES + INPUT_SIZE * 4 + 16;  // 160 KB + mbars
    cudaFuncSetAttribute(logic_kernel,
                         cudaFuncAttributeMaxDynamicSharedMemorySize, smem);

    coeff_kernel<<<(NUM_NEURONS * 16) / 256, 256>>>(w);
    logic_kernel<<<GRID, THREADS, smem>>>(x, conn, out);
}